// round 2
// baseline (speedup 1.0000x reference)
#include <cuda_runtime.h>
#include <cstdint>

// Embedding gather: out[i] = table[ids_flat[i]], i in [0, N), D = 64 fp32.
// ids are int32 (JAX default without x64 despite dtype=jnp.int64 in source).
// 16 threads per row, one float4 per thread -> 256B per row, line-granular
// gather reads and fully coalesced stores.

__global__ void __launch_bounds__(256, 8)
embed_gather_kernel(const int* __restrict__ ids,
                    const float4* __restrict__ table4,   // [VOCAB, 16] float4
                    float4* __restrict__ out4,           // [N, 16] float4
                    int n_rows, int vocab)
{
    long long gidx = (long long)blockIdx.x * blockDim.x + threadIdx.x;
    long long total = (long long)n_rows * 16;
    if (gidx >= total) return;

    int row   = (int)(gidx >> 4);
    int chunk = (int)(gidx & 15);

    int id = __ldg(&ids[row]);                 // broadcast within half-warp
    // Defensive: if dtype interpretation is wrong, fail with wrong values,
    // not an illegal access.
    if ((unsigned)id >= (unsigned)vocab) id = 0;

    out4[gidx] = __ldg(table4 + (long long)id * 16 + chunk);
}

extern "C" void kernel_launch(void* const* d_in, const int* in_sizes, int n_in,
                              void* d_out, int out_size)
{
    // inputs (metadata order): ids [BATCH*HIST] int32, table [VOCAB*64] float32
    const int*    ids   = (const int*)d_in[0];
    const float4* table = (const float4*)d_in[1];
    float4*       out   = (float4*)d_out;

    int n_rows = in_sizes[0];                  // 16384*50 = 819200
    int vocab  = in_sizes[1] / 64;             // table rows = 1,000,000

    long long total4 = (long long)n_rows * 16;
    int threads = 256;
    int blocks  = (int)((total4 + threads - 1) / threads);
    embed_gather_kernel<<<blocks, threads>>>(ids, table, out, n_rows, vocab);
}

// round 3
// speedup vs baseline: 1.2438x; 1.2438x over previous
#include <cuda_runtime.h>
#include <cstdint>

// Embedding gather: out[i] = table[ids_flat[i]], D = 64 fp32 (256B/row).
// - 16 threads per row, one float4 per thread: line-granular gather reads,
//   fully coalesced stores.
// - Output written with __stcs (evict-first streaming store) so the 210MB
//   output stream does not evict table lines from L2 (repeat ids ~31%).
// - Each thread handles TWO chunks (from rows total/2 apart): 2 independent
//   gather LDGs in flight per thread for latency hiding.

__global__ void __launch_bounds__(256, 8)
embed_gather_kernel(const int* __restrict__ ids,
                    const float4* __restrict__ table4,   // [VOCAB, 16] float4
                    float4* __restrict__ out4,           // [N, 16] float4
                    int n_rows, int vocab)
{
    long long total  = (long long)n_rows * 16;          // total float4 chunks
    long long half   = total >> 1;                      // n_rows is even here
    long long g      = (long long)blockIdx.x * blockDim.x + threadIdx.x;

    if (g < half) {
        long long g0 = g;
        long long g1 = g + half;

        int row0 = (int)(g0 >> 4), chunk0 = (int)(g0 & 15);
        int row1 = (int)(g1 >> 4), chunk1 = (int)(g1 & 15);

        int id0 = __ldg(&ids[row0]);
        int id1 = __ldg(&ids[row1]);
        if ((unsigned)id0 >= (unsigned)vocab) id0 = 0;
        if ((unsigned)id1 >= (unsigned)vocab) id1 = 0;

        // Two independent gathers in flight.
        float4 v0 = __ldg(table4 + (long long)id0 * 16 + chunk0);
        float4 v1 = __ldg(table4 + (long long)id1 * 16 + chunk1);

        __stcs(out4 + g0, v0);      // streaming store: don't pollute L2
        __stcs(out4 + g1, v1);
    } else if (g < total) {
        // Tail path for odd totals (not hit with these shapes, kept for safety).
        int row = (int)(g >> 4), chunk = (int)(g & 15);
        int id = __ldg(&ids[row]);
        if ((unsigned)id >= (unsigned)vocab) id = 0;
        __stcs(out4 + g, __ldg(table4 + (long long)id * 16 + chunk));
    }
}

extern "C" void kernel_launch(void* const* d_in, const int* in_sizes, int n_in,
                              void* d_out, int out_size)
{
    const int*    ids   = (const int*)d_in[0];
    const float4* table = (const float4*)d_in[1];
    float4*       out   = (float4*)d_out;

    int n_rows = in_sizes[0];                  // 819200
    int vocab  = in_sizes[1] / 64;             // 1,000,000

    long long total4 = (long long)n_rows * 16; // 13,107,200 chunks
    long long nthreads = (total4 + 1) >> 1;    // 2 chunks per thread

    int threads = 256;
    int blocks  = (int)((nthreads + threads - 1) / threads);
    embed_gather_kernel<<<blocks, threads>>>(ids, table, out, n_rows, vocab);
}

// round 4
// speedup vs baseline: 1.2838x; 1.0322x over previous
#include <cuda_runtime.h>
#include <cstdint>

// Embedding gather: out[i] = table[ids_flat[i]], D = 64 fp32 (256B/row).
// - 16 threads per row-chunk, one float4 per thread.
// - 4 independent gathers per thread (quarters of the index space) with
//   front-batched loads: 4 id LDGs, then 4 table LDG.128s in flight, then
//   4 streaming stores. Deepens DRAM queue occupancy (MLP_p1=4).
// - __stcs output stores keep the table L2-resident (repeat ids hit L2).

__global__ void __launch_bounds__(256, 8)
embed_gather_kernel(const int* __restrict__ ids,
                    const float4* __restrict__ table4,   // [VOCAB, 16] float4
                    float4* __restrict__ out4,           // [N, 16] float4
                    int n_rows, int vocab)
{
    long long total = (long long)n_rows * 16;            // total float4 chunks
    long long q     = total >> 2;                        // divisible: n_rows%4==0
    long long g     = (long long)blockIdx.x * blockDim.x + threadIdx.x;

    if (g < q) {
        long long g0 = g, g1 = g + q, g2 = g + 2 * q, g3 = g + 3 * q;

        // Batch id loads (4 independent LDGs).
        int id0 = __ldg(&ids[(int)(g0 >> 4)]);
        int id1 = __ldg(&ids[(int)(g1 >> 4)]);
        int id2 = __ldg(&ids[(int)(g2 >> 4)]);
        int id3 = __ldg(&ids[(int)(g3 >> 4)]);
        if ((unsigned)id0 >= (unsigned)vocab) id0 = 0;
        if ((unsigned)id1 >= (unsigned)vocab) id1 = 0;
        if ((unsigned)id2 >= (unsigned)vocab) id2 = 0;
        if ((unsigned)id3 >= (unsigned)vocab) id3 = 0;

        int c0 = (int)(g0 & 15), c1 = (int)(g1 & 15);
        int c2 = (int)(g2 & 15), c3 = (int)(g3 & 15);

        // 4 independent gathers in flight.
        float4 v0 = __ldg(table4 + (long long)id0 * 16 + c0);
        float4 v1 = __ldg(table4 + (long long)id1 * 16 + c1);
        float4 v2 = __ldg(table4 + (long long)id2 * 16 + c2);
        float4 v3 = __ldg(table4 + (long long)id3 * 16 + c3);

        __stcs(out4 + g0, v0);
        __stcs(out4 + g1, v1);
        __stcs(out4 + g2, v2);
        __stcs(out4 + g3, v3);
    } else {
        // Tail for totals not divisible by 4 (not hit with these shapes).
        long long rem = 4 * q + (g - q);
        if (rem < total) {
            int row = (int)(rem >> 4), chunk = (int)(rem & 15);
            int id = __ldg(&ids[row]);
            if ((unsigned)id >= (unsigned)vocab) id = 0;
            __stcs(out4 + rem, __ldg(table4 + (long long)id * 16 + chunk));
        }
    }
}

extern "C" void kernel_launch(void* const* d_in, const int* in_sizes, int n_in,
                              void* d_out, int out_size)
{
    const int*    ids   = (const int*)d_in[0];
    const float4* table = (const float4*)d_in[1];
    float4*       out   = (float4*)d_out;

    int n_rows = in_sizes[0];                  // 819200
    int vocab  = in_sizes[1] / 64;             // 1,000,000

    long long total4   = (long long)n_rows * 16;     // 13,107,200
    long long q        = total4 >> 2;
    long long tail     = total4 - 4 * q;             // 0..3
    long long nthreads = q + tail;

    int threads = 256;
    int blocks  = (int)((nthreads + threads - 1) / threads);
    embed_gather_kernel<<<blocks, threads>>>(ids, table, out, n_rows, vocab);
}